// round 15
// baseline (speedup 1.0000x reference)
#include <cuda_runtime.h>
#include <cuda_bf16.h>
#include <cstdint>

#define N_TOK 8192
#define D_DIM 4096
#define E_EXP 8
#define R_RANK 16
#define EJ (E_EXP * R_RANK)   // 128
#define SCALING_F 2.0f

// ---------------- device-global scratch (no allocation allowed) --------------
__device__ float          g_wfull[N_TOK * E_EXP];
__device__ __nv_bfloat16  g_xhi[(size_t)N_TOK * D_DIM];
__device__ __nv_bfloat16  g_xlo[(size_t)N_TOK * D_DIM];
__device__ __nv_bfloat16  g_whi[(size_t)D_DIM * D_DIM];
__device__ __nv_bfloat16  g_wlo[(size_t)D_DIM * D_DIM];
__device__ __nv_bfloat16  g_abf[(size_t)EJ * D_DIM];     // A as [j=e*16+r][D] bf16
__device__ __nv_bfloat16  g_tbf[(size_t)N_TOK * EJ];     // t in bf16 [8192][128]
__device__ __nv_bfloat16  g_bcatT[(size_t)D_DIM * EJ];   // BcatT[d][j=e*16+r]

// ---------------- helpers ----------------------------------------------------
__device__ __forceinline__ uint32_t smem_u32(const void* p) {
    uint32_t a;
    asm("{ .reg .u64 t; cvta.to.shared.u64 t, %1; cvt.u32.u64 %0, t; }" : "=r"(a) : "l"(p));
    return a;
}
__device__ __forceinline__ void cp16(uint32_t dst, const void* src) {
    asm volatile("cp.async.cg.shared.global [%0], [%1], 16;" :: "r"(dst), "l"(src));
}
__device__ __forceinline__ void cp_commit() {
    asm volatile("cp.async.commit_group;" ::: "memory");
}
__device__ __forceinline__ void cp_wait1() {
    asm volatile("cp.async.wait_group 1;" ::: "memory");
}
__device__ __forceinline__ void ldm4(uint32_t* r, uint32_t addr) {
    asm volatile("ldmatrix.sync.aligned.m8n8.x4.shared.b16 {%0,%1,%2,%3}, [%4];"
                 : "=r"(r[0]), "=r"(r[1]), "=r"(r[2]), "=r"(r[3]) : "r"(addr));
}
__device__ __forceinline__ void mma_bf16(float* c, const uint32_t* a, uint32_t b0,
                                         uint32_t b1) {
    asm volatile(
        "mma.sync.aligned.m16n8k16.row.col.f32.bf16.bf16.f32 "
        "{%0,%1,%2,%3}, {%4,%5,%6,%7}, {%8,%9}, {%0,%1,%2,%3};"
        : "+f"(c[0]), "+f"(c[1]), "+f"(c[2]), "+f"(c[3])
        : "r"(a[0]), "r"(a[1]), "r"(a[2]), "r"(a[3]), "r"(b0), "r"(b1));
}
__device__ __forceinline__ uint32_t pack_bf2(float a, float b) {
    __nv_bfloat162 t = __floats2bfloat162_rn(a, b);
    return *reinterpret_cast<uint32_t*>(&t);
}

// ---------------- prep: split x, split W, BcatT, A->bf16 (ONE kernel) --------
#define NX4 ((N_TOK * D_DIM) / 4)            // 8388608 float4 units
#define NW4 ((D_DIM * D_DIM) / 4)            // 4194304
#define NBC (D_DIM * EJ)                     // 524288
#define NA4 ((EJ * D_DIM) / 4)               // 131072
#define NPREP (NX4 + NW4 + NBC + NA4)

__device__ __forceinline__ void split4(const float* __restrict__ src,
                                       __nv_bfloat16* __restrict__ hi,
                                       __nv_bfloat16* __restrict__ lo, int i) {
    float4 v = ((const float4*)src)[i];
    __nv_bfloat16 h0 = __float2bfloat16_rn(v.x), h1 = __float2bfloat16_rn(v.y);
    __nv_bfloat16 h2 = __float2bfloat16_rn(v.z), h3 = __float2bfloat16_rn(v.w);
    uint2 ph, pl;
    {
        __nv_bfloat162 a = {h0, h1}, b = {h2, h3};
        ph.x = *reinterpret_cast<uint32_t*>(&a);
        ph.y = *reinterpret_cast<uint32_t*>(&b);
    }
    pl.x = pack_bf2(v.x - __bfloat162float(h0), v.y - __bfloat162float(h1));
    pl.y = pack_bf2(v.z - __bfloat162float(h2), v.w - __bfloat162float(h3));
    ((uint2*)hi)[i] = ph;
    ((uint2*)lo)[i] = pl;
}

__global__ __launch_bounds__(256) void prep_kernel(const float* __restrict__ x,
                                                   const float* __restrict__ W,
                                                   const float* __restrict__ B,
                                                   const float* __restrict__ A) {
    for (int i = blockIdx.x * blockDim.x + threadIdx.x; i < NPREP;
         i += gridDim.x * blockDim.x) {
        if (i < NX4) {
            split4(x, g_xhi, g_xlo, i);
        } else if (i < NX4 + NW4) {
            split4(W, g_whi, g_wlo, i - NX4);
        } else if (i < NX4 + NW4 + NBC) {
            int j2 = i - NX4 - NW4;               // [0, 4096*128)
            int d = j2 >> 7, j = j2 & 127, e = j >> 4, r = j & 15;
            g_bcatT[(size_t)d * EJ + j] = __float2bfloat16_rn(
                B[(size_t)e * D_DIM * R_RANK + (size_t)d * R_RANK + r]);
        } else {
            int i4 = i - NX4 - NW4 - NBC;         // A flat is already [j][d]
            float4 v = ((const float4*)A)[i4];
            uint2 p;
            p.x = pack_bf2(v.x, v.y);
            p.y = pack_bf2(v.z, v.w);
            ((uint2*)g_abf)[i4] = p;
        }
    }
}

// ---------------- gate: logits + top-k softmax -> g_wfull --------------------
__global__ __launch_bounds__(128) void gate_kernel(const float* __restrict__ x,
                                                   const float* __restrict__ gw,
                                                   const int* __restrict__ topk_p) {
    __shared__ float sgw[E_EXP][512];
    const int warp = threadIdx.x >> 5, lane = threadIdx.x & 31;
    const int n = blockIdx.x * 4 + warp;

    float acc[E_EXP];
#pragma unroll
    for (int e = 0; e < E_EXP; e++) acc[e] = 0.f;

    for (int kt = 0; kt < D_DIM / 512; kt++) {
        __syncthreads();
        for (int i = threadIdx.x; i < E_EXP * 128; i += blockDim.x) {
            int e = i >> 7, kv = i & 127;
            ((float4*)sgw[e])[kv] = ((const float4*)(gw + e * D_DIM + kt * 512))[kv];
        }
        __syncthreads();
        const float4* xr = (const float4*)(x + (size_t)n * D_DIM + kt * 512);
#pragma unroll 4
        for (int k4 = lane; k4 < 128; k4 += 32) {
            float4 xv = xr[k4];
#pragma unroll
            for (int e = 0; e < E_EXP; e++) {
                float4 wv = ((float4*)sgw[e])[k4];
                acc[e] += xv.x * wv.x + xv.y * wv.y + xv.z * wv.z + xv.w * wv.w;
            }
        }
    }
#pragma unroll
    for (int e = 0; e < E_EXP; e++)
#pragma unroll
        for (int off = 16; off; off >>= 1)
            acc[e] += __shfl_xor_sync(0xffffffffu, acc[e], off);

    if (lane == 0) {
        const int K = *topk_p;
        bool sel[E_EXP];
        int idxs[E_EXP];
#pragma unroll
        for (int e = 0; e < E_EXP; e++) sel[e] = false;
        for (int t = 0; t < K; t++) {
            int best = 0;
            float bv = -3.0e38f;
            for (int e = 0; e < E_EXP; e++)
                if (!sel[e] && acc[e] > bv) { bv = acc[e]; best = e; }
            sel[best] = true;
            idxs[t] = best;
        }
        float mx = acc[idxs[0]];
        for (int t = 1; t < K; t++) mx = fmaxf(mx, acc[idxs[t]]);
        float p[E_EXP], s = 0.f;
        for (int t = 0; t < K; t++) { p[t] = expf(acc[idxs[t]] - mx); s += p[t]; }
        float inv = 1.0f / s;
        for (int e = 0; e < E_EXP; e++) g_wfull[n * E_EXP + e] = 0.f;
        for (int t = 0; t < K; t++) g_wfull[n * E_EXP + idxs[t]] = SCALING_F * p[t] * inv;
    }
}

// ---------------- t = (xhi @ Abf^T) * wfull  via mma -> bf16 (R13) -----------
#define T_ROWB 80
#define T_XHI_O 0
#define T_AB_O 10240
#define T_STAGE 20480
#define T_NCH 128

__device__ __forceinline__ void t_load(int c, int buf, int bm, uint32_t sm) {
    const uint32_t sb = sm + buf * T_STAGE;
    const int tid = threadIdx.x;
    const char* xh = (const char*)g_xhi;
    const char* ab = (const char*)g_abf;
    const size_t kofs = (size_t)c * 64;  // bytes into 8192B row
#pragma unroll
    for (int t = 0; t < 4; t++) {
        int idx = tid + t * 256;
        int j = idx & 511, row = j >> 2, seg = j & 3;
        if (idx < 512)
            cp16(sb + T_XHI_O + row * T_ROWB + seg * 16,
                 xh + (size_t)(bm + row) * 8192 + kofs + seg * 16);
        else
            cp16(sb + T_AB_O + row * T_ROWB + seg * 16,
                 ab + (size_t)row * 8192 + kofs + seg * 16);
    }
    cp_commit();
}

__global__ __launch_bounds__(256, 2) void t_mma_kernel() {
    extern __shared__ char smem[];
    const uint32_t sm = smem_u32(smem);
    const int tid = threadIdx.x;
    const int wid = tid >> 5, lane = tid & 31;
    const int wm = wid & 3, wn = wid >> 2;          // 4x2 warp grid
    const int bm = blockIdx.x * 128;

    const int lrow = (lane & 7) + ((lane >> 3) & 1) * 8;
    const int lkh = (lane >> 4) * 16;

    float acc[2][8][4];
#pragma unroll
    for (int mt = 0; mt < 2; mt++)
#pragma unroll
        for (int j = 0; j < 8; j++)
#pragma unroll
            for (int q = 0; q < 4; q++) acc[mt][j][q] = 0.f;

    t_load(0, 0, bm, sm);
    t_load(1, 1, bm, sm);

    for (int c = 0; c < T_NCH; c++) {
        const int buf = c & 1;
        cp_wait1();
        __syncthreads();

        const uint32_t sb = sm + buf * T_STAGE;
        const uint32_t a_base = sb + T_XHI_O + (wm * 32 + lrow) * T_ROWB + lkh;
        const uint32_t b_base = sb + T_AB_O + (wn * 64 + lrow) * T_ROWB + lkh;

#pragma unroll
        for (int s = 0; s < 2; s++) {
            const uint32_t so = s * 32;
            uint32_t ah[2][4], b[4][4];
#pragma unroll
            for (int mt = 0; mt < 2; mt++) ldm4(ah[mt], a_base + mt * 16 * T_ROWB + so);
#pragma unroll
            for (int nt = 0; nt < 4; nt++) ldm4(b[nt], b_base + nt * 16 * T_ROWB + so);
#pragma unroll
            for (int mt = 0; mt < 2; mt++)
#pragma unroll
                for (int nt = 0; nt < 4; nt++) {
                    mma_bf16(acc[mt][nt * 2 + 0], ah[mt], b[nt][0], b[nt][2]);
                    mma_bf16(acc[mt][nt * 2 + 1], ah[mt], b[nt][1], b[nt][3]);
                }
        }
        __syncthreads();
        if (c + 2 < T_NCH) t_load(c + 2, buf, bm, sm);
        else cp_commit();
    }

    // epilogue: scale by routing weight (includes SCALING), pack bf16
    const int r0 = bm + wm * 32 + (lane >> 2);
    const int col0 = wn * 64 + (lane & 3) * 2;
#pragma unroll
    for (int mt = 0; mt < 2; mt++)
#pragma unroll
        for (int j = 0; j < 8; j++) {
            int r = r0 + mt * 16;
            int cc = col0 + j * 8;           // cc even; cc,cc+1 share expert
            int e = cc >> 4;
            float w1 = g_wfull[r * E_EXP + e];
            float w2 = g_wfull[(r + 8) * E_EXP + e];
            *(uint32_t*)&g_tbf[(size_t)r * EJ + cc] =
                pack_bf2(acc[mt][j][0] * w1, acc[mt][j][1] * w1);
            *(uint32_t*)&g_tbf[(size_t)(r + 8) * EJ + cc] =
                pack_bf2(acc[mt][j][2] * w2, acc[mt][j][3] * w2);
        }
}

// ---------------- main mma.sync GEMM -----------------------------------------
// y[bm:+128, bn:+128] = xhi@Whi^T + xhi@Wlo^T + xlo@Whi^T  (K=4096)
//                     + t @ BcatT^T                         (K=128, hi only)
// 256 thr (4x2 warps, 32x64 warp tile), BK=32, exact 64B rows + XOR swizzle,
// 3-stage pipeline at 2 CTAs/SM, ONE barrier/chunk.
// NEW (R15): loop unrolled by 3 -> stage buffer index is a COMPILE-TIME
// constant, so all smem addresses fold to base+imm (kills %3 + IMAD chains).
#define ROWB 64
#define AHI_O 0
#define ALO_O 8192
#define BHI_O 16384
#define BLO_O 24576
#define STAGE_B 32768
#define NCH 132        // 128 main + 4 lora chunks; 132 = 3*44
#define DSMEM_TOTAL (3 * STAGE_B)

__device__ __forceinline__ void load_stage(int c, int buf, int bm, int bn, uint32_t sm) {
    const uint32_t sb = sm + buf * STAGE_B;
    const int tid = threadIdx.x;
    if (c < 128) {
        const char* xh = (const char*)g_xhi;
        const char* xl = (const char*)g_xlo;
        const char* wh = (const char*)g_whi;
        const char* wl = (const char*)g_wlo;
        const size_t kofs = (size_t)c * 64;  // bytes into 8192B row
#pragma unroll
        for (int t = 0; t < 8; t++) {
            int idx = tid + t * 256;
            int j = idx & 511, row = j >> 2, seg = j & 3;
            int region = idx >> 9;
            int segp = seg ^ ((row >> 1) & 3);  // XOR swizzle
            uint32_t dst = sb + region * 8192 + row * ROWB + segp * 16;
            const char* src;
            if (region == 0)      src = xh + (size_t)(bm + row) * 8192 + kofs + seg * 16;
            else if (region == 1) src = xl + (size_t)(bm + row) * 8192 + kofs + seg * 16;
            else if (region == 2) src = wh + (size_t)(bn + row) * 8192 + kofs + seg * 16;
            else                  src = wl + (size_t)(bn + row) * 8192 + kofs + seg * 16;
            cp16(dst, src);
        }
    } else {
        const char* tp = (const char*)g_tbf;
        const char* bp = (const char*)g_bcatT;
        const size_t kofs = (size_t)(c - 128) * 64;  // bytes into 256B row
#pragma unroll
        for (int t = 0; t < 4; t++) {
            int idx = tid + t * 256;
            int j = idx & 511, row = j >> 2, seg = j & 3;
            int segp = seg ^ ((row >> 1) & 3);
            if (idx < 512)
                cp16(sb + AHI_O + row * ROWB + segp * 16,
                     tp + (size_t)(bm + row) * 256 + kofs + seg * 16);
            else
                cp16(sb + BHI_O + row * ROWB + segp * 16,
                     bp + (size_t)(bn + row) * 256 + kofs + seg * 16);
        }
    }
    cp_commit();
}

struct MainCtx {
    uint32_t sm;
    int bm, bn;
    uint32_t arow_off, alrow_off, brow_off, blrow_off;  // per-thread row offsets
    uint32_t co0, co1;                                  // swizzled 16B offsets s=0/1
};

// One pipeline step with compile-time stage buffer BUF.
template <int BUF>
__device__ __forceinline__ void main_step(int c, float acc[2][8][4], const MainCtx& X) {
    cp_wait1();          // group c complete (c+1 may be in flight)
    __syncthreads();     // (a) group-c visible; (b) compute(c-1) done everywhere
    if (c + 2 < NCH) load_stage(c + 2, (BUF + 2) % 3, X.bm, X.bn, X.sm);
    else cp_commit();    // keep group accounting uniform

    const bool lora = (c >= 128);
    const uint32_t sb = X.sm + BUF * STAGE_B;   // compile-time offset from sm
    const uint32_t a_row = sb + X.arow_off;
    const uint32_t al_row = sb + X.alrow_off;
    const uint32_t b_row = sb + X.brow_off;
    const uint32_t bl_row = sb + X.blrow_off;

#pragma unroll
    for (int s = 0; s < 2; s++) {
        const uint32_t co = s ? X.co1 : X.co0;
        uint32_t ah[2][4], al[2][4], b[4][4];
#pragma unroll
        for (int mt = 0; mt < 2; mt++) ldm4(ah[mt], a_row + mt * 16 * ROWB + co);
        if (!lora)
#pragma unroll
            for (int mt = 0; mt < 2; mt++) ldm4(al[mt], al_row + mt * 16 * ROWB + co);
#pragma unroll
        for (int nt = 0; nt < 4; nt++) ldm4(b[nt], b_row + nt * 16 * ROWB + co);
        // hi*hi
#pragma unroll
        for (int mt = 0; mt < 2; mt++)
#pragma unroll
            for (int nt = 0; nt < 4; nt++) {
                mma_bf16(acc[mt][nt * 2 + 0], ah[mt], b[nt][0], b[nt][2]);
                mma_bf16(acc[mt][nt * 2 + 1], ah[mt], b[nt][1], b[nt][3]);
            }
        if (!lora) {
            // lo*hi
#pragma unroll
            for (int mt = 0; mt < 2; mt++)
#pragma unroll
                for (int nt = 0; nt < 4; nt++) {
                    mma_bf16(acc[mt][nt * 2 + 0], al[mt], b[nt][0], b[nt][2]);
                    mma_bf16(acc[mt][nt * 2 + 1], al[mt], b[nt][1], b[nt][3]);
                }
            // hi*lo: reload b from Wlo
#pragma unroll
            for (int nt = 0; nt < 4; nt++) ldm4(b[nt], bl_row + nt * 16 * ROWB + co);
#pragma unroll
            for (int mt = 0; mt < 2; mt++)
#pragma unroll
                for (int nt = 0; nt < 4; nt++) {
                    mma_bf16(acc[mt][nt * 2 + 0], ah[mt], b[nt][0], b[nt][2]);
                    mma_bf16(acc[mt][nt * 2 + 1], ah[mt], b[nt][1], b[nt][3]);
                }
        }
    }
    // no trailing barrier: next step's top-of-loop sync provides ordering
}

__global__ __launch_bounds__(256, 2) void main_mma_kernel(float* __restrict__ y) {
    extern __shared__ char smem[];
    const int tid = threadIdx.x;
    const int wid = tid >> 5, lane = tid & 31;
    const int wm = wid & 3, wn = wid >> 2;          // 4x2 warp grid

    const int lrow = (lane & 7) + ((lane >> 3) & 1) * 8;
    const int lk = lane >> 4;                        // logical 16B chunk (0/1)
    const int sw = (lrow >> 1) & 3;                  // per-lane swizzle key

    MainCtx X;
    X.sm = smem_u32(smem);
    X.bm = blockIdx.y * 128;
    X.bn = blockIdx.x * 128;
    X.arow_off = AHI_O + (wm * 32 + lrow) * ROWB;
    X.alrow_off = ALO_O + (wm * 32 + lrow) * ROWB;
    X.brow_off = BHI_O + (wn * 64 + lrow) * ROWB;
    X.blrow_off = BLO_O + (wn * 64 + lrow) * ROWB;
    X.co0 = (uint32_t)(((0 << 1 | lk) ^ sw) * 16);
    X.co1 = (uint32_t)(((1 << 1 | lk) ^ sw) * 16);

    float acc[2][8][4];
#pragma unroll
    for (int mt = 0; mt < 2; mt++)
#pragma unroll
        for (int j = 0; j < 8; j++)
#pragma unroll
            for (int q = 0; q < 4; q++) acc[mt][j][q] = 0.f;

    load_stage(0, 0, X.bm, X.bn, X.sm);
    load_stage(1, 1, X.bm, X.bn, X.sm);

    // unroll-by-3: buffer index is compile-time in each step
    for (int cg = 0; cg < NCH; cg += 3) {
        main_step<0>(cg + 0, acc, X);
        main_step<1>(cg + 1, acc, X);
        main_step<2>(cg + 2, acc, X);
    }

    // ---- epilogue: fragment -> y ----
    const int r0 = X.bm + wm * 32 + (lane >> 2);
    const int col0 = X.bn + wn * 64 + (lane & 3) * 2;
#pragma unroll
    for (int mt = 0; mt < 2; mt++)
#pragma unroll
        for (int j = 0; j < 8; j++) {
            int r = r0 + mt * 16;
            int cc = col0 + j * 8;
            *(float2*)&y[(size_t)r * D_DIM + cc] = make_float2(acc[mt][j][0], acc[mt][j][1]);
            *(float2*)&y[(size_t)(r + 8) * D_DIM + cc] = make_float2(acc[mt][j][2], acc[mt][j][3]);
        }
}

// -----------------------------------------------------------------------------
extern "C" void kernel_launch(void* const* d_in, const int* in_sizes, int n_in,
                              void* d_out, int out_size) {
    const float* x = (const float*)d_in[0];
    const float* base_W = (const float*)d_in[1];
    const float* gate_W = (const float*)d_in[2];
    const float* A = (const float*)d_in[3];
    const float* B = (const float*)d_in[4];
    const int* topk = (const int*)d_in[5];
    float* y = (float*)d_out;

    cudaFuncSetAttribute(main_mma_kernel, cudaFuncAttributeMaxDynamicSharedMemorySize,
                         DSMEM_TOTAL);
    cudaFuncSetAttribute(t_mma_kernel, cudaFuncAttributeMaxDynamicSharedMemorySize,
                         2 * T_STAGE);

    // 4 launches: main_mma_kernel stays on ncu's -s 5 profile slot.
    prep_kernel<<<2048, 256>>>(x, base_W, B, A);
    gate_kernel<<<N_TOK / 4, 128>>>(x, gate_W, topk);
    t_mma_kernel<<<N_TOK / 128, 256, 2 * T_STAGE>>>();
    main_mma_kernel<<<dim3(D_DIM / 128, N_TOK / 128), 256, DSMEM_TOTAL>>>(y);
}

// round 16
// speedup vs baseline: 1.0383x; 1.0383x over previous
#include <cuda_runtime.h>
#include <cuda_bf16.h>
#include <cstdint>

#define N_TOK 8192
#define D_DIM 4096
#define E_EXP 8
#define R_RANK 16
#define EJ (E_EXP * R_RANK)   // 128
#define SCALING_F 2.0f

// ---------------- device-global scratch (no allocation allowed) --------------
__device__ float          g_wfull[N_TOK * E_EXP];
__device__ __nv_bfloat16  g_xhi[(size_t)N_TOK * D_DIM];
__device__ __nv_bfloat16  g_xlo[(size_t)N_TOK * D_DIM];
__device__ __nv_bfloat16  g_whi[(size_t)D_DIM * D_DIM];
__device__ __nv_bfloat16  g_wlo[(size_t)D_DIM * D_DIM];
__device__ __nv_bfloat16  g_abf[(size_t)EJ * D_DIM];     // A as [j=e*16+r][D] bf16
__device__ __nv_bfloat16  g_tbf[(size_t)N_TOK * EJ];     // t in bf16 [8192][128]
__device__ __nv_bfloat16  g_bcatT[(size_t)D_DIM * EJ];   // BcatT[d][j=e*16+r]

// ---------------- helpers ----------------------------------------------------
__device__ __forceinline__ uint32_t smem_u32(const void* p) {
    uint32_t a;
    asm("{ .reg .u64 t; cvta.to.shared.u64 t, %1; cvt.u32.u64 %0, t; }" : "=r"(a) : "l"(p));
    return a;
}
__device__ __forceinline__ void cp16(uint32_t dst, const void* src) {
    asm volatile("cp.async.cg.shared.global [%0], [%1], 16;" :: "r"(dst), "l"(src));
}
__device__ __forceinline__ void cp_commit() {
    asm volatile("cp.async.commit_group;" ::: "memory");
}
__device__ __forceinline__ void cp_wait1() {
    asm volatile("cp.async.wait_group 1;" ::: "memory");
}
__device__ __forceinline__ void ldm4(uint32_t* r, uint32_t addr) {
    asm volatile("ldmatrix.sync.aligned.m8n8.x4.shared.b16 {%0,%1,%2,%3}, [%4];"
                 : "=r"(r[0]), "=r"(r[1]), "=r"(r[2]), "=r"(r[3]) : "r"(addr));
}
__device__ __forceinline__ void mma_bf16(float* c, const uint32_t* a, uint32_t b0,
                                         uint32_t b1) {
    asm volatile(
        "mma.sync.aligned.m16n8k16.row.col.f32.bf16.bf16.f32 "
        "{%0,%1,%2,%3}, {%4,%5,%6,%7}, {%8,%9}, {%0,%1,%2,%3};"
        : "+f"(c[0]), "+f"(c[1]), "+f"(c[2]), "+f"(c[3])
        : "r"(a[0]), "r"(a[1]), "r"(a[2]), "r"(a[3]), "r"(b0), "r"(b1));
}
__device__ __forceinline__ uint32_t pack_bf2(float a, float b) {
    __nv_bfloat162 t = __floats2bfloat162_rn(a, b);
    return *reinterpret_cast<uint32_t*>(&t);
}

// ---------------- fused prep + gate ------------------------------------------
// Blocks [0, PREP_BLKS): split x, split W, BcatT, A->bf16 (grid-stride).
// Blocks [PREP_BLKS, PREP_BLKS+GATE_BLKS): gate logits + top-k softmax.
// Independent data -> overlap DRAM-bound prep with L1-bound gate.
#define NX4 ((N_TOK * D_DIM) / 4)            // 8388608 float4 units
#define NW4 ((D_DIM * D_DIM) / 4)            // 4194304
#define NBC (D_DIM * EJ)                     // 524288
#define NA4 ((EJ * D_DIM) / 4)               // 131072
#define NPREP (NX4 + NW4 + NBC + NA4)
#define PREP_BLKS 2048
#define GATE_BLKS (N_TOK / 8)                // 1024: 8 tokens per 256-thr block

__device__ __forceinline__ void split4(const float* __restrict__ src,
                                       __nv_bfloat16* __restrict__ hi,
                                       __nv_bfloat16* __restrict__ lo, int i) {
    float4 v = ((const float4*)src)[i];
    __nv_bfloat16 h0 = __float2bfloat16_rn(v.x), h1 = __float2bfloat16_rn(v.y);
    __nv_bfloat16 h2 = __float2bfloat16_rn(v.z), h3 = __float2bfloat16_rn(v.w);
    uint2 ph, pl;
    {
        __nv_bfloat162 a = {h0, h1}, b = {h2, h3};
        ph.x = *reinterpret_cast<uint32_t*>(&a);
        ph.y = *reinterpret_cast<uint32_t*>(&b);
    }
    pl.x = pack_bf2(v.x - __bfloat162float(h0), v.y - __bfloat162float(h1));
    pl.y = pack_bf2(v.z - __bfloat162float(h2), v.w - __bfloat162float(h3));
    ((uint2*)hi)[i] = ph;
    ((uint2*)lo)[i] = pl;
}

__global__ __launch_bounds__(256) void prep_gate_kernel(const float* __restrict__ x,
                                                        const float* __restrict__ W,
                                                        const float* __restrict__ B,
                                                        const float* __restrict__ A,
                                                        const float* __restrict__ gw,
                                                        const int* __restrict__ topk_p) {
    __shared__ float sgw[E_EXP][512];   // used by gate blocks only (16 KB)

    if (blockIdx.x < PREP_BLKS) {
        for (int i = blockIdx.x * blockDim.x + threadIdx.x; i < NPREP;
             i += PREP_BLKS * blockDim.x) {
            if (i < NX4) {
                split4(x, g_xhi, g_xlo, i);
            } else if (i < NX4 + NW4) {
                split4(W, g_whi, g_wlo, i - NX4);
            } else if (i < NX4 + NW4 + NBC) {
                int j2 = i - NX4 - NW4;           // [0, 4096*128)
                int d = j2 >> 7, j = j2 & 127, e = j >> 4, r = j & 15;
                g_bcatT[(size_t)d * EJ + j] = __float2bfloat16_rn(
                    B[(size_t)e * D_DIM * R_RANK + (size_t)d * R_RANK + r]);
            } else {
                int i4 = i - NX4 - NW4 - NBC;     // A flat is already [j][d]
                float4 v = ((const float4*)A)[i4];
                uint2 p;
                p.x = pack_bf2(v.x, v.y);
                p.y = pack_bf2(v.z, v.w);
                ((uint2*)g_abf)[i4] = p;
            }
        }
        return;
    }

    // ---- gate blocks: 8 warps, one token per warp ----
    const int gb = blockIdx.x - PREP_BLKS;
    const int warp = threadIdx.x >> 5, lane = threadIdx.x & 31;
    const int n = gb * 8 + warp;

    float acc[E_EXP];
#pragma unroll
    for (int e = 0; e < E_EXP; e++) acc[e] = 0.f;

    for (int kt = 0; kt < D_DIM / 512; kt++) {
        __syncthreads();
        for (int i = threadIdx.x; i < E_EXP * 128; i += blockDim.x) {
            int e = i >> 7, kv = i & 127;
            ((float4*)sgw[e])[kv] = ((const float4*)(gw + e * D_DIM + kt * 512))[kv];
        }
        __syncthreads();
        const float4* xr = (const float4*)(x + (size_t)n * D_DIM + kt * 512);
#pragma unroll 4
        for (int k4 = lane; k4 < 128; k4 += 32) {
            float4 xv = xr[k4];
#pragma unroll
            for (int e = 0; e < E_EXP; e++) {
                float4 wv = ((float4*)sgw[e])[k4];
                acc[e] += xv.x * wv.x + xv.y * wv.y + xv.z * wv.z + xv.w * wv.w;
            }
        }
    }
#pragma unroll
    for (int e = 0; e < E_EXP; e++)
#pragma unroll
        for (int off = 16; off; off >>= 1)
            acc[e] += __shfl_xor_sync(0xffffffffu, acc[e], off);

    if (lane == 0) {
        const int K = *topk_p;
        bool sel[E_EXP];
        int idxs[E_EXP];
#pragma unroll
        for (int e = 0; e < E_EXP; e++) sel[e] = false;
        for (int t = 0; t < K; t++) {
            int best = 0;
            float bv = -3.0e38f;
            for (int e = 0; e < E_EXP; e++)
                if (!sel[e] && acc[e] > bv) { bv = acc[e]; best = e; }
            sel[best] = true;
            idxs[t] = best;
        }
        float mx = acc[idxs[0]];
        for (int t = 1; t < K; t++) mx = fmaxf(mx, acc[idxs[t]]);
        float p[E_EXP], s = 0.f;
        for (int t = 0; t < K; t++) { p[t] = expf(acc[idxs[t]] - mx); s += p[t]; }
        float inv = 1.0f / s;
        for (int e = 0; e < E_EXP; e++) g_wfull[n * E_EXP + e] = 0.f;
        for (int t = 0; t < K; t++) g_wfull[n * E_EXP + idxs[t]] = SCALING_F * p[t] * inv;
    }
}

// ---------------- t = (xhi @ Abf^T) * wfull  via mma -> bf16 (R13) -----------
#define T_ROWB 80
#define T_XHI_O 0
#define T_AB_O 10240
#define T_STAGE 20480
#define T_NCH 128

__device__ __forceinline__ void t_load(int c, int buf, int bm, uint32_t sm) {
    const uint32_t sb = sm + buf * T_STAGE;
    const int tid = threadIdx.x;
    const char* xh = (const char*)g_xhi;
    const char* ab = (const char*)g_abf;
    const size_t kofs = (size_t)c * 64;  // bytes into 8192B row
#pragma unroll
    for (int t = 0; t < 4; t++) {
        int idx = tid + t * 256;
        int j = idx & 511, row = j >> 2, seg = j & 3;
        if (idx < 512)
            cp16(sb + T_XHI_O + row * T_ROWB + seg * 16,
                 xh + (size_t)(bm + row) * 8192 + kofs + seg * 16);
        else
            cp16(sb + T_AB_O + row * T_ROWB + seg * 16,
                 ab + (size_t)row * 8192 + kofs + seg * 16);
    }
    cp_commit();
}

__global__ __launch_bounds__(256, 2) void t_mma_kernel() {
    extern __shared__ char smem[];
    const uint32_t sm = smem_u32(smem);
    const int tid = threadIdx.x;
    const int wid = tid >> 5, lane = tid & 31;
    const int wm = wid & 3, wn = wid >> 2;          // 4x2 warp grid
    const int bm = blockIdx.x * 128;

    const int lrow = (lane & 7) + ((lane >> 3) & 1) * 8;
    const int lkh = (lane >> 4) * 16;

    float acc[2][8][4];
#pragma unroll
    for (int mt = 0; mt < 2; mt++)
#pragma unroll
        for (int j = 0; j < 8; j++)
#pragma unroll
            for (int q = 0; q < 4; q++) acc[mt][j][q] = 0.f;

    t_load(0, 0, bm, sm);
    t_load(1, 1, bm, sm);

    for (int c = 0; c < T_NCH; c++) {
        const int buf = c & 1;
        cp_wait1();
        __syncthreads();

        const uint32_t sb = sm + buf * T_STAGE;
        const uint32_t a_base = sb + T_XHI_O + (wm * 32 + lrow) * T_ROWB + lkh;
        const uint32_t b_base = sb + T_AB_O + (wn * 64 + lrow) * T_ROWB + lkh;

#pragma unroll
        for (int s = 0; s < 2; s++) {
            const uint32_t so = s * 32;
            uint32_t ah[2][4], b[4][4];
#pragma unroll
            for (int mt = 0; mt < 2; mt++) ldm4(ah[mt], a_base + mt * 16 * T_ROWB + so);
#pragma unroll
            for (int nt = 0; nt < 4; nt++) ldm4(b[nt], b_base + nt * 16 * T_ROWB + so);
#pragma unroll
            for (int mt = 0; mt < 2; mt++)
#pragma unroll
                for (int nt = 0; nt < 4; nt++) {
                    mma_bf16(acc[mt][nt * 2 + 0], ah[mt], b[nt][0], b[nt][2]);
                    mma_bf16(acc[mt][nt * 2 + 1], ah[mt], b[nt][1], b[nt][3]);
                }
        }
        __syncthreads();
        if (c + 2 < T_NCH) t_load(c + 2, buf, bm, sm);
        else cp_commit();
    }

    // epilogue: scale by routing weight (includes SCALING), pack bf16
    const int r0 = bm + wm * 32 + (lane >> 2);
    const int col0 = wn * 64 + (lane & 3) * 2;
#pragma unroll
    for (int mt = 0; mt < 2; mt++)
#pragma unroll
        for (int j = 0; j < 8; j++) {
            int r = r0 + mt * 16;
            int cc = col0 + j * 8;           // cc even; cc,cc+1 share expert
            int e = cc >> 4;
            float w1 = g_wfull[r * E_EXP + e];
            float w2 = g_wfull[(r + 8) * E_EXP + e];
            *(uint32_t*)&g_tbf[(size_t)r * EJ + cc] =
                pack_bf2(acc[mt][j][0] * w1, acc[mt][j][1] * w1);
            *(uint32_t*)&g_tbf[(size_t)(r + 8) * EJ + cc] =
                pack_bf2(acc[mt][j][2] * w2, acc[mt][j][3] * w2);
        }
}

// ---------------- main mma.sync GEMM (R14-identical, best known) -------------
// y[bm:+128, bn:+128] = xhi@Whi^T + xhi@Wlo^T + xlo@Whi^T  (K=4096)
//                     + t @ BcatT^T                         (K=128, hi only)
// 256 thr (4x2 warps, 32x64 warp tile), BK=32, exact 64B rows + XOR swizzle,
// 3-stage pipeline at 2 CTAs/SM, ONE barrier/chunk (runtime buf = c % 3).
#define ROWB 64
#define AHI_O 0
#define ALO_O 8192
#define BHI_O 16384
#define BLO_O 24576
#define STAGE_B 32768
#define NCH 132        // 128 main + 4 lora chunks
#define DSMEM_TOTAL (3 * STAGE_B)

__device__ __forceinline__ void load_stage(int c, int buf, int bm, int bn, uint32_t sm) {
    const uint32_t sb = sm + buf * STAGE_B;
    const int tid = threadIdx.x;
    if (c < 128) {
        const char* xh = (const char*)g_xhi;
        const char* xl = (const char*)g_xlo;
        const char* wh = (const char*)g_whi;
        const char* wl = (const char*)g_wlo;
        const size_t kofs = (size_t)c * 64;  // bytes into 8192B row
#pragma unroll
        for (int t = 0; t < 8; t++) {
            int idx = tid + t * 256;
            int j = idx & 511, row = j >> 2, seg = j & 3;
            int region = idx >> 9;
            int segp = seg ^ ((row >> 1) & 3);  // XOR swizzle
            uint32_t dst = sb + region * 8192 + row * ROWB + segp * 16;
            const char* src;
            if (region == 0)      src = xh + (size_t)(bm + row) * 8192 + kofs + seg * 16;
            else if (region == 1) src = xl + (size_t)(bm + row) * 8192 + kofs + seg * 16;
            else if (region == 2) src = wh + (size_t)(bn + row) * 8192 + kofs + seg * 16;
            else                  src = wl + (size_t)(bn + row) * 8192 + kofs + seg * 16;
            cp16(dst, src);
        }
    } else {
        const char* tp = (const char*)g_tbf;
        const char* bp = (const char*)g_bcatT;
        const size_t kofs = (size_t)(c - 128) * 64;  // bytes into 256B row
#pragma unroll
        for (int t = 0; t < 4; t++) {
            int idx = tid + t * 256;
            int j = idx & 511, row = j >> 2, seg = j & 3;
            int segp = seg ^ ((row >> 1) & 3);
            if (idx < 512)
                cp16(sb + AHI_O + row * ROWB + segp * 16,
                     tp + (size_t)(bm + row) * 256 + kofs + seg * 16);
            else
                cp16(sb + BHI_O + row * ROWB + segp * 16,
                     bp + (size_t)(bn + row) * 256 + kofs + seg * 16);
        }
    }
    cp_commit();
}

__global__ __launch_bounds__(256, 2) void main_mma_kernel(float* __restrict__ y) {
    extern __shared__ char smem[];
    const uint32_t sm = smem_u32(smem);
    const int tid = threadIdx.x;
    const int wid = tid >> 5, lane = tid & 31;
    const int wm = wid & 3, wn = wid >> 2;          // 4x2 warp grid
    const int bm = blockIdx.y * 128, bn = blockIdx.x * 128;

    const int lrow = (lane & 7) + ((lane >> 3) & 1) * 8;
    const int lk = lane >> 4;                        // logical 16B chunk (0/1)
    const int sw = (lrow >> 1) & 3;                  // per-lane swizzle key

    float acc[2][8][4];
#pragma unroll
    for (int mt = 0; mt < 2; mt++)
#pragma unroll
        for (int j = 0; j < 8; j++)
#pragma unroll
            for (int q = 0; q < 4; q++) acc[mt][j][q] = 0.f;

    load_stage(0, 0, bm, bn, sm);
    load_stage(1, 1, bm, bn, sm);

    for (int c = 0; c < NCH; c++) {
        const int buf = c % 3;
        cp_wait1();          // group c complete (c+1 may be in flight)
        __syncthreads();     // (a) group-c visible to all; (b) compute(c-1) done
        // safe now: buffer (c+2)%3 == (c-1)%3 was last used by compute(c-1)
        if (c + 2 < NCH) load_stage(c + 2, (c + 2) % 3, bm, bn, sm);
        else cp_commit();    // keep group accounting uniform

        const bool lora = (c >= 128);
        const uint32_t sb = sm + buf * STAGE_B;
        const uint32_t a_row = sb + AHI_O + (wm * 32 + lrow) * ROWB;
        const uint32_t al_row = sb + ALO_O + (wm * 32 + lrow) * ROWB;
        const uint32_t b_row = sb + BHI_O + (wn * 64 + lrow) * ROWB;
        const uint32_t bl_row = sb + BLO_O + (wn * 64 + lrow) * ROWB;

#pragma unroll
        for (int s = 0; s < 2; s++) {
            const uint32_t co = (uint32_t)((((s << 1) | lk) ^ sw) * 16);
            uint32_t ah[2][4], al[2][4], b[4][4];
#pragma unroll
            for (int mt = 0; mt < 2; mt++) ldm4(ah[mt], a_row + mt * 16 * ROWB + co);
            if (!lora)
#pragma unroll
                for (int mt = 0; mt < 2; mt++) ldm4(al[mt], al_row + mt * 16 * ROWB + co);
#pragma unroll
            for (int nt = 0; nt < 4; nt++) ldm4(b[nt], b_row + nt * 16 * ROWB + co);
            // hi*hi
#pragma unroll
            for (int mt = 0; mt < 2; mt++)
#pragma unroll
                for (int nt = 0; nt < 4; nt++) {
                    mma_bf16(acc[mt][nt * 2 + 0], ah[mt], b[nt][0], b[nt][2]);
                    mma_bf16(acc[mt][nt * 2 + 1], ah[mt], b[nt][1], b[nt][3]);
                }
            if (!lora) {
                // lo*hi
#pragma unroll
                for (int mt = 0; mt < 2; mt++)
#pragma unroll
                    for (int nt = 0; nt < 4; nt++) {
                        mma_bf16(acc[mt][nt * 2 + 0], al[mt], b[nt][0], b[nt][2]);
                        mma_bf16(acc[mt][nt * 2 + 1], al[mt], b[nt][1], b[nt][3]);
                    }
                // hi*lo: reload b from Wlo
#pragma unroll
                for (int nt = 0; nt < 4; nt++) ldm4(b[nt], bl_row + nt * 16 * ROWB + co);
#pragma unroll
                for (int mt = 0; mt < 2; mt++)
#pragma unroll
                    for (int nt = 0; nt < 4; nt++) {
                        mma_bf16(acc[mt][nt * 2 + 0], ah[mt], b[nt][0], b[nt][2]);
                        mma_bf16(acc[mt][nt * 2 + 1], ah[mt], b[nt][1], b[nt][3]);
                    }
            }
        }
        // no trailing barrier: next iter's top-of-loop sync provides ordering
    }

    // ---- epilogue: fragment -> y ----
    const int r0 = bm + wm * 32 + (lane >> 2);
    const int col0 = bn + wn * 64 + (lane & 3) * 2;
#pragma unroll
    for (int mt = 0; mt < 2; mt++)
#pragma unroll
        for (int j = 0; j < 8; j++) {
            int r = r0 + mt * 16;
            int cc = col0 + j * 8;
            *(float2*)&y[(size_t)r * D_DIM + cc] = make_float2(acc[mt][j][0], acc[mt][j][1]);
            *(float2*)&y[(size_t)(r + 8) * D_DIM + cc] = make_float2(acc[mt][j][2], acc[mt][j][3]);
        }
}

// -----------------------------------------------------------------------------
extern "C" void kernel_launch(void* const* d_in, const int* in_sizes, int n_in,
                              void* d_out, int out_size) {
    const float* x = (const float*)d_in[0];
    const float* base_W = (const float*)d_in[1];
    const float* gate_W = (const float*)d_in[2];
    const float* A = (const float*)d_in[3];
    const float* B = (const float*)d_in[4];
    const int* topk = (const int*)d_in[5];
    float* y = (float*)d_out;

    cudaFuncSetAttribute(main_mma_kernel, cudaFuncAttributeMaxDynamicSharedMemorySize,
                         DSMEM_TOTAL);
    cudaFuncSetAttribute(t_mma_kernel, cudaFuncAttributeMaxDynamicSharedMemorySize,
                         2 * T_STAGE);

    // 3 launches (+2 harness) -> main_mma_kernel is launch idx 4... keep 4
    // launches so main stays on ncu's -s 5 slot: pad with a no-op? No — the
    // profile slot moving to t_mma is acceptable this round; main is stable.
    prep_gate_kernel<<<PREP_BLKS + GATE_BLKS, 256>>>(x, base_W, B, A, gate_W, topk);
    t_mma_kernel<<<N_TOK / 128, 256, 2 * T_STAGE>>>();
    main_mma_kernel<<<dim3(D_DIM / 128, N_TOK / 128), 256, DSMEM_TOTAL>>>(y);
}

// round 17
// speedup vs baseline: 1.0885x; 1.0484x over previous
#include <cuda_runtime.h>
#include <cuda_bf16.h>
#include <cstdint>

#define N_TOK 8192
#define D_DIM 4096
#define E_EXP 8
#define R_RANK 16
#define EJ (E_EXP * R_RANK)   // 128
#define SCALING_F 2.0f

// ---------------- device-global scratch (no allocation allowed) --------------
__device__ float          g_wfull[N_TOK * E_EXP];
__device__ __nv_bfloat16  g_xhi[(size_t)N_TOK * D_DIM];
__device__ __nv_bfloat16  g_xlo[(size_t)N_TOK * D_DIM];
__device__ __nv_bfloat16  g_whi[(size_t)D_DIM * D_DIM];
__device__ __nv_bfloat16  g_wlo[(size_t)D_DIM * D_DIM];
__device__ __nv_bfloat16  g_abf[(size_t)EJ * D_DIM];     // A as [j=e*16+r][D] bf16
__device__ __nv_bfloat16  g_tbf[(size_t)N_TOK * EJ];     // t in bf16 [8192][128]
__device__ __nv_bfloat16  g_bcatT[(size_t)D_DIM * EJ];   // BcatT[d][j=e*16+r]
__device__ int            g_tdone;                        // t-CTA completion count

// ---------------- helpers ----------------------------------------------------
__device__ __forceinline__ uint32_t smem_u32(const void* p) {
    uint32_t a;
    asm("{ .reg .u64 t; cvta.to.shared.u64 t, %1; cvt.u32.u64 %0, t; }" : "=r"(a) : "l"(p));
    return a;
}
__device__ __forceinline__ void cp16(uint32_t dst, const void* src) {
    asm volatile("cp.async.cg.shared.global [%0], [%1], 16;" :: "r"(dst), "l"(src));
}
__device__ __forceinline__ void cp_commit() {
    asm volatile("cp.async.commit_group;" ::: "memory");
}
__device__ __forceinline__ void cp_wait1() {
    asm volatile("cp.async.wait_group 1;" ::: "memory");
}
__device__ __forceinline__ void ldm4(uint32_t* r, uint32_t addr) {
    asm volatile("ldmatrix.sync.aligned.m8n8.x4.shared.b16 {%0,%1,%2,%3}, [%4];"
                 : "=r"(r[0]), "=r"(r[1]), "=r"(r[2]), "=r"(r[3]) : "r"(addr));
}
__device__ __forceinline__ void mma_bf16(float* c, const uint32_t* a, uint32_t b0,
                                         uint32_t b1) {
    asm volatile(
        "mma.sync.aligned.m16n8k16.row.col.f32.bf16.bf16.f32 "
        "{%0,%1,%2,%3}, {%4,%5,%6,%7}, {%8,%9}, {%0,%1,%2,%3};"
        : "+f"(c[0]), "+f"(c[1]), "+f"(c[2]), "+f"(c[3])
        : "r"(a[0]), "r"(a[1]), "r"(a[2]), "r"(a[3]), "r"(b0), "r"(b1));
}
__device__ __forceinline__ uint32_t pack_bf2(float a, float b) {
    __nv_bfloat162 t = __floats2bfloat162_rn(a, b);
    return *reinterpret_cast<uint32_t*>(&t);
}

// ---------------- fused prep + gate (R16) ------------------------------------
#define NX4 ((N_TOK * D_DIM) / 4)            // 8388608 float4 units
#define NW4 ((D_DIM * D_DIM) / 4)            // 4194304
#define NBC (D_DIM * EJ)                     // 524288
#define NA4 ((EJ * D_DIM) / 4)               // 131072
#define NPREP (NX4 + NW4 + NBC + NA4)
#define PREP_BLKS 2048
#define GATE_BLKS (N_TOK / 8)                // 1024: 8 tokens per 256-thr block

__device__ __forceinline__ void split4(const float* __restrict__ src,
                                       __nv_bfloat16* __restrict__ hi,
                                       __nv_bfloat16* __restrict__ lo, int i) {
    float4 v = ((const float4*)src)[i];
    __nv_bfloat16 h0 = __float2bfloat16_rn(v.x), h1 = __float2bfloat16_rn(v.y);
    __nv_bfloat16 h2 = __float2bfloat16_rn(v.z), h3 = __float2bfloat16_rn(v.w);
    uint2 ph, pl;
    {
        __nv_bfloat162 a = {h0, h1}, b = {h2, h3};
        ph.x = *reinterpret_cast<uint32_t*>(&a);
        ph.y = *reinterpret_cast<uint32_t*>(&b);
    }
    pl.x = pack_bf2(v.x - __bfloat162float(h0), v.y - __bfloat162float(h1));
    pl.y = pack_bf2(v.z - __bfloat162float(h2), v.w - __bfloat162float(h3));
    ((uint2*)hi)[i] = ph;
    ((uint2*)lo)[i] = pl;
}

__global__ __launch_bounds__(256) void prep_gate_kernel(const float* __restrict__ x,
                                                        const float* __restrict__ W,
                                                        const float* __restrict__ B,
                                                        const float* __restrict__ A,
                                                        const float* __restrict__ gw,
                                                        const int* __restrict__ topk_p) {
    __shared__ float sgw[E_EXP][512];   // used by gate blocks only (16 KB)

    if (blockIdx.x == 0 && threadIdx.x == 0) g_tdone = 0;  // reset handshake

    if (blockIdx.x < PREP_BLKS) {
        for (int i = blockIdx.x * blockDim.x + threadIdx.x; i < NPREP;
             i += PREP_BLKS * blockDim.x) {
            if (i < NX4) {
                split4(x, g_xhi, g_xlo, i);
            } else if (i < NX4 + NW4) {
                split4(W, g_whi, g_wlo, i - NX4);
            } else if (i < NX4 + NW4 + NBC) {
                int j2 = i - NX4 - NW4;           // [0, 4096*128)
                int d = j2 >> 7, j = j2 & 127, e = j >> 4, r = j & 15;
                g_bcatT[(size_t)d * EJ + j] = __float2bfloat16_rn(
                    B[(size_t)e * D_DIM * R_RANK + (size_t)d * R_RANK + r]);
            } else {
                int i4 = i - NX4 - NW4 - NBC;     // A flat is already [j][d]
                float4 v = ((const float4*)A)[i4];
                uint2 p;
                p.x = pack_bf2(v.x, v.y);
                p.y = pack_bf2(v.z, v.w);
                ((uint2*)g_abf)[i4] = p;
            }
        }
        return;
    }

    // ---- gate blocks: 8 warps, one token per warp ----
    const int gb = blockIdx.x - PREP_BLKS;
    const int warp = threadIdx.x >> 5, lane = threadIdx.x & 31;
    const int n = gb * 8 + warp;

    float acc[E_EXP];
#pragma unroll
    for (int e = 0; e < E_EXP; e++) acc[e] = 0.f;

    for (int kt = 0; kt < D_DIM / 512; kt++) {
        __syncthreads();
        for (int i = threadIdx.x; i < E_EXP * 128; i += blockDim.x) {
            int e = i >> 7, kv = i & 127;
            ((float4*)sgw[e])[kv] = ((const float4*)(gw + e * D_DIM + kt * 512))[kv];
        }
        __syncthreads();
        const float4* xr = (const float4*)(x + (size_t)n * D_DIM + kt * 512);
#pragma unroll 4
        for (int k4 = lane; k4 < 128; k4 += 32) {
            float4 xv = xr[k4];
#pragma unroll
            for (int e = 0; e < E_EXP; e++) {
                float4 wv = ((float4*)sgw[e])[k4];
                acc[e] += xv.x * wv.x + xv.y * wv.y + xv.z * wv.z + xv.w * wv.w;
            }
        }
    }
#pragma unroll
    for (int e = 0; e < E_EXP; e++)
#pragma unroll
        for (int off = 16; off; off >>= 1)
            acc[e] += __shfl_xor_sync(0xffffffffu, acc[e], off);

    if (lane == 0) {
        const int K = *topk_p;
        bool sel[E_EXP];
        int idxs[E_EXP];
#pragma unroll
        for (int e = 0; e < E_EXP; e++) sel[e] = false;
        for (int t = 0; t < K; t++) {
            int best = 0;
            float bv = -3.0e38f;
            for (int e = 0; e < E_EXP; e++)
                if (!sel[e] && acc[e] > bv) { bv = acc[e]; best = e; }
            sel[best] = true;
            idxs[t] = best;
        }
        float mx = acc[idxs[0]];
        for (int t = 1; t < K; t++) mx = fmaxf(mx, acc[idxs[t]]);
        float p[E_EXP], s = 0.f;
        for (int t = 0; t < K; t++) { p[t] = expf(acc[idxs[t]] - mx); s += p[t]; }
        float inv = 1.0f / s;
        for (int e = 0; e < E_EXP; e++) g_wfull[n * E_EXP + e] = 0.f;
        for (int t = 0; t < K; t++) g_wfull[n * E_EXP + idxs[t]] = SCALING_F * p[t] * inv;
    }
}

// ---------------- t tile loader (shares main's smem) -------------------------
#define T_ROWB 80
#define T_XHI_O 0
#define T_AB_O 10240
#define T_STAGE 20480
#define T_NCH 128

__device__ __forceinline__ void t_load(int c, int buf, int bm, uint32_t sm) {
    const uint32_t sb = sm + buf * T_STAGE;
    const int tid = threadIdx.x;
    const char* xh = (const char*)g_xhi;
    const char* ab = (const char*)g_abf;
    const size_t kofs = (size_t)c * 64;  // bytes into 8192B row
#pragma unroll
    for (int t = 0; t < 4; t++) {
        int idx = tid + t * 256;
        int j = idx & 511, row = j >> 2, seg = j & 3;
        if (idx < 512)
            cp16(sb + T_XHI_O + row * T_ROWB + seg * 16,
                 xh + (size_t)(bm + row) * 8192 + kofs + seg * 16);
        else
            cp16(sb + T_AB_O + row * T_ROWB + seg * 16,
                 ab + (size_t)row * 8192 + kofs + seg * 16);
    }
    cp_commit();
}

// t-CTA body: t = (xhi @ Abf^T) * wfull -> g_tbf, then signal completion.
__device__ void t_path(uint32_t sm, int bm) {
    const int tid = threadIdx.x;
    const int wid = tid >> 5, lane = tid & 31;
    const int wm = wid & 3, wn = wid >> 2;          // 4x2 warp grid

    const int lrow = (lane & 7) + ((lane >> 3) & 1) * 8;
    const int lkh = (lane >> 4) * 16;

    float acc[2][8][4];
#pragma unroll
    for (int mt = 0; mt < 2; mt++)
#pragma unroll
        for (int j = 0; j < 8; j++)
#pragma unroll
            for (int q = 0; q < 4; q++) acc[mt][j][q] = 0.f;

    t_load(0, 0, bm, sm);
    t_load(1, 1, bm, sm);

    for (int c = 0; c < T_NCH; c++) {
        const int buf = c & 1;
        cp_wait1();
        __syncthreads();

        const uint32_t sb = sm + buf * T_STAGE;
        const uint32_t a_base = sb + T_XHI_O + (wm * 32 + lrow) * T_ROWB + lkh;
        const uint32_t b_base = sb + T_AB_O + (wn * 64 + lrow) * T_ROWB + lkh;

#pragma unroll
        for (int s = 0; s < 2; s++) {
            const uint32_t so = s * 32;
            uint32_t ah[2][4], b[4][4];
#pragma unroll
            for (int mt = 0; mt < 2; mt++) ldm4(ah[mt], a_base + mt * 16 * T_ROWB + so);
#pragma unroll
            for (int nt = 0; nt < 4; nt++) ldm4(b[nt], b_base + nt * 16 * T_ROWB + so);
#pragma unroll
            for (int mt = 0; mt < 2; mt++)
#pragma unroll
                for (int nt = 0; nt < 4; nt++) {
                    mma_bf16(acc[mt][nt * 2 + 0], ah[mt], b[nt][0], b[nt][2]);
                    mma_bf16(acc[mt][nt * 2 + 1], ah[mt], b[nt][1], b[nt][3]);
                }
        }
        __syncthreads();
        if (c + 2 < T_NCH) t_load(c + 2, buf, bm, sm);
        else cp_commit();
    }

    // epilogue: scale by routing weight (includes SCALING), pack bf16
    const int r0 = bm + wm * 32 + (lane >> 2);
    const int col0 = wn * 64 + (lane & 3) * 2;
#pragma unroll
    for (int mt = 0; mt < 2; mt++)
#pragma unroll
        for (int j = 0; j < 8; j++) {
            int r = r0 + mt * 16;
            int cc = col0 + j * 8;           // cc even; cc,cc+1 share expert
            int e = cc >> 4;
            float w1 = g_wfull[r * E_EXP + e];
            float w2 = g_wfull[(r + 8) * E_EXP + e];
            *(uint32_t*)&g_tbf[(size_t)r * EJ + cc] =
                pack_bf2(acc[mt][j][0] * w1, acc[mt][j][1] * w1);
            *(uint32_t*)&g_tbf[(size_t)(r + 8) * EJ + cc] =
                pack_bf2(acc[mt][j][2] * w2, acc[mt][j][3] * w2);
        }

    // publish: all stores visible, then one arrival
    __threadfence();
    __syncthreads();
    if (tid == 0) atomicAdd(&g_tdone, 1);
}

// ---------------- main mma.sync GEMM (R14 structure) -------------------------
// Grid is 1D: bids [0,64) = t-CTAs (wave-1 prologue), bids [64, 64+2048) = main.
// Main CTAs consume g_tbf only from chunk 128 (prefetched at c==126), guarded
// by a handshake on g_tdone (expected to never actually spin).
#define ROWB 64
#define AHI_O 0
#define ALO_O 8192
#define BHI_O 16384
#define BLO_O 24576
#define STAGE_B 32768
#define NCH 132        // 128 main + 4 lora chunks
#define DSMEM_TOTAL (3 * STAGE_B)
#define T_CTAS 64

__device__ __forceinline__ void load_stage(int c, int buf, int bm, int bn, uint32_t sm) {
    const uint32_t sb = sm + buf * STAGE_B;
    const int tid = threadIdx.x;
    if (c < 128) {
        const char* xh = (const char*)g_xhi;
        const char* xl = (const char*)g_xlo;
        const char* wh = (const char*)g_whi;
        const char* wl = (const char*)g_wlo;
        const size_t kofs = (size_t)c * 64;  // bytes into 8192B row
#pragma unroll
        for (int t = 0; t < 8; t++) {
            int idx = tid + t * 256;
            int j = idx & 511, row = j >> 2, seg = j & 3;
            int region = idx >> 9;
            int segp = seg ^ ((row >> 1) & 3);  // XOR swizzle
            uint32_t dst = sb + region * 8192 + row * ROWB + segp * 16;
            const char* src;
            if (region == 0)      src = xh + (size_t)(bm + row) * 8192 + kofs + seg * 16;
            else if (region == 1) src = xl + (size_t)(bm + row) * 8192 + kofs + seg * 16;
            else if (region == 2) src = wh + (size_t)(bn + row) * 8192 + kofs + seg * 16;
            else                  src = wl + (size_t)(bn + row) * 8192 + kofs + seg * 16;
            cp16(dst, src);
        }
    } else {
        const char* tp = (const char*)g_tbf;
        const char* bp = (const char*)g_bcatT;
        const size_t kofs = (size_t)(c - 128) * 64;  // bytes into 256B row
#pragma unroll
        for (int t = 0; t < 4; t++) {
            int idx = tid + t * 256;
            int j = idx & 511, row = j >> 2, seg = j & 3;
            int segp = seg ^ ((row >> 1) & 3);
            if (idx < 512)
                cp16(sb + AHI_O + row * ROWB + segp * 16,
                     tp + (size_t)(bm + row) * 256 + kofs + seg * 16);
            else
                cp16(sb + BHI_O + row * ROWB + segp * 16,
                     bp + (size_t)(bn + row) * 256 + kofs + seg * 16);
        }
    }
    cp_commit();
}

__global__ __launch_bounds__(256, 2) void main_mma_kernel(float* __restrict__ y) {
    extern __shared__ char smem[];
    const uint32_t sm = smem_u32(smem);
    const int tid = threadIdx.x;

    if (blockIdx.x < T_CTAS) {           // wave-1 prologue: compute t tile
        t_path(sm, blockIdx.x * 128);
        return;
    }

    const int bid2 = blockIdx.x - T_CTAS;
    const int wid = tid >> 5, lane = tid & 31;
    const int wm = wid & 3, wn = wid >> 2;          // 4x2 warp grid
    const int bm = (bid2 >> 5) * 128, bn = (bid2 & 31) * 128;

    const int lrow = (lane & 7) + ((lane >> 3) & 1) * 8;
    const int lk = lane >> 4;                        // logical 16B chunk (0/1)
    const int sw = (lrow >> 1) & 3;                  // per-lane swizzle key

    float acc[2][8][4];
#pragma unroll
    for (int mt = 0; mt < 2; mt++)
#pragma unroll
        for (int j = 0; j < 8; j++)
#pragma unroll
            for (int q = 0; q < 4; q++) acc[mt][j][q] = 0.f;

    load_stage(0, 0, bm, bn, sm);
    load_stage(1, 1, bm, bn, sm);

    for (int c = 0; c < NCH; c++) {
        const int buf = c % 3;
        cp_wait1();          // group c complete (c+1 may be in flight)
        __syncthreads();     // (a) group-c visible to all; (b) compute(c-1) done

        if (c == 126) {      // about to prefetch chunk 128 (g_tbf): ensure t done
            if (tid == 0) {
                while (*(volatile int*)&g_tdone < T_CTAS) __nanosleep(64);
                __threadfence();
            }
            __syncthreads();
        }
        if (c + 2 < NCH) load_stage(c + 2, (c + 2) % 3, bm, bn, sm);
        else cp_commit();    // keep group accounting uniform

        const bool lora = (c >= 128);
        const uint32_t sb = sm + buf * STAGE_B;
        const uint32_t a_row = sb + AHI_O + (wm * 32 + lrow) * ROWB;
        const uint32_t al_row = sb + ALO_O + (wm * 32 + lrow) * ROWB;
        const uint32_t b_row = sb + BHI_O + (wn * 64 + lrow) * ROWB;
        const uint32_t bl_row = sb + BLO_O + (wn * 64 + lrow) * ROWB;

#pragma unroll
        for (int s = 0; s < 2; s++) {
            const uint32_t co = (uint32_t)((((s << 1) | lk) ^ sw) * 16);
            uint32_t ah[2][4], al[2][4], b[4][4];
#pragma unroll
            for (int mt = 0; mt < 2; mt++) ldm4(ah[mt], a_row + mt * 16 * ROWB + co);
            if (!lora)
#pragma unroll
                for (int mt = 0; mt < 2; mt++) ldm4(al[mt], al_row + mt * 16 * ROWB + co);
#pragma unroll
            for (int nt = 0; nt < 4; nt++) ldm4(b[nt], b_row + nt * 16 * ROWB + co);
            // hi*hi
#pragma unroll
            for (int mt = 0; mt < 2; mt++)
#pragma unroll
                for (int nt = 0; nt < 4; nt++) {
                    mma_bf16(acc[mt][nt * 2 + 0], ah[mt], b[nt][0], b[nt][2]);
                    mma_bf16(acc[mt][nt * 2 + 1], ah[mt], b[nt][1], b[nt][3]);
                }
            if (!lora) {
                // lo*hi
#pragma unroll
                for (int mt = 0; mt < 2; mt++)
#pragma unroll
                    for (int nt = 0; nt < 4; nt++) {
                        mma_bf16(acc[mt][nt * 2 + 0], al[mt], b[nt][0], b[nt][2]);
                        mma_bf16(acc[mt][nt * 2 + 1], al[mt], b[nt][1], b[nt][3]);
                    }
                // hi*lo: reload b from Wlo
#pragma unroll
                for (int nt = 0; nt < 4; nt++) ldm4(b[nt], bl_row + nt * 16 * ROWB + co);
#pragma unroll
                for (int mt = 0; mt < 2; mt++)
#pragma unroll
                    for (int nt = 0; nt < 4; nt++) {
                        mma_bf16(acc[mt][nt * 2 + 0], ah[mt], b[nt][0], b[nt][2]);
                        mma_bf16(acc[mt][nt * 2 + 1], ah[mt], b[nt][1], b[nt][3]);
                    }
            }
        }
        // no trailing barrier: next iter's top-of-loop sync provides ordering
    }

    // ---- epilogue: fragment -> y ----
    const int r0 = bm + wm * 32 + (lane >> 2);
    const int col0 = bn + wn * 64 + (lane & 3) * 2;
#pragma unroll
    for (int mt = 0; mt < 2; mt++)
#pragma unroll
        for (int j = 0; j < 8; j++) {
            int r = r0 + mt * 16;
            int cc = col0 + j * 8;
            *(float2*)&y[(size_t)r * D_DIM + cc] = make_float2(acc[mt][j][0], acc[mt][j][1]);
            *(float2*)&y[(size_t)(r + 8) * D_DIM + cc] = make_float2(acc[mt][j][2], acc[mt][j][3]);
        }
}

// -----------------------------------------------------------------------------
extern "C" void kernel_launch(void* const* d_in, const int* in_sizes, int n_in,
                              void* d_out, int out_size) {
    const float* x = (const float*)d_in[0];
    const float* base_W = (const float*)d_in[1];
    const float* gate_W = (const float*)d_in[2];
    const float* A = (const float*)d_in[3];
    const float* B = (const float*)d_in[4];
    const int* topk = (const int*)d_in[5];
    float* y = (float*)d_out;

    cudaFuncSetAttribute(main_mma_kernel, cudaFuncAttributeMaxDynamicSharedMemorySize,
                         DSMEM_TOTAL);

    // 2 launches: t-GEMM rides inside main's grid as wave-1 prologue CTAs.
    prep_gate_kernel<<<PREP_BLKS + GATE_BLKS, 256>>>(x, base_W, B, A, gate_W, topk);
    main_mma_kernel<<<T_CTAS + 2048, 256, DSMEM_TOTAL>>>(y);
}